// round 15
// baseline (speedup 1.0000x reference)
#include <cuda_runtime.h>
#include <cuda_bf16.h>
#include <cstdint>

// ---------------- problem constants ----------------
#define N_EXPERTS 8
#define TOKENS    8192
#define KDIM      2048
#define ODIM      2048

#define BM 128
#define BN 128
#define BK 64                      // 64 bf16 = 128B per smem row
#define MT (TOKENS / BM)           // 64 worst-case m-tiles per expert
#define NT (ODIM / BN)             // 16
#define NCHUNK (KDIM / BK)         // 32
#define NTHREADS 1024              // 32 warps -> 8/SMSP (2x latency cover vs R13)
#define STAGES 4
#define A_STAGE_BYTES (BM * 128)   // 16384
#define STAGE_BYTES   (2 * A_STAGE_BYTES)               // 32768
#define SMEM_DYN_BYTES (STAGES * STAGE_BYTES + 128)     // 131200, 1 CTA/SM

// ---------------- device scratch ----------------
__device__ int g_counts[N_EXPERTS];
__device__ int g_bucket[N_EXPERTS * TOKENS];
__device__ __nv_bfloat16 g_xs[TOKENS * KDIM];                 // expert-sorted bf16 x
__device__ __nv_bfloat16 g_ws[N_EXPERTS * ODIM * KDIM];       // bf16 weights

// ---------------- helpers ----------------
__device__ __forceinline__ uint32_t smem_u32(const void* p) {
    uint32_t a;
    asm("{ .reg .u64 t; cvta.to.shared.u64 t, %1; cvt.u32.u64 %0, t; }" : "=r"(a) : "l"(p));
    return a;
}
__device__ __forceinline__ uint32_t pack_bf16(float a, float b) {
    __nv_bfloat162 h = __floats2bfloat162_rn(a, b);
    return *reinterpret_cast<uint32_t*>(&h);
}
__device__ __forceinline__ float bf16_round(float v) {
    return __bfloat162float(__float2bfloat16_rn(v));
}

#define CP_ASYNC_CG(dst, src) \
    asm volatile("cp.async.cg.shared.global [%0], [%1], 16;" :: "r"(dst), "l"(src))
#define CP_COMMIT() asm volatile("cp.async.commit_group;" ::: "memory")
#define CP_WAIT2()  asm volatile("cp.async.wait_group 2;"  ::: "memory")

__device__ __forceinline__ void ldsm_x4(uint32_t addr, uint32_t& r0, uint32_t& r1,
                                        uint32_t& r2, uint32_t& r3) {
    asm volatile("ldmatrix.sync.aligned.m8n8.x4.shared.b16 {%0, %1, %2, %3}, [%4];"
                 : "=r"(r0), "=r"(r1), "=r"(r2), "=r"(r3) : "r"(addr));
}
__device__ __forceinline__ void mma_16816(float* d, const uint32_t* a, const uint32_t* b) {
    asm volatile(
        "mma.sync.aligned.m16n8k16.row.col.f32.bf16.bf16.f32 "
        "{%0, %1, %2, %3}, {%4, %5, %6, %7}, {%8, %9}, {%0, %1, %2, %3};"
        : "+f"(d[0]), "+f"(d[1]), "+f"(d[2]), "+f"(d[3])
        : "r"(a[0]), "r"(a[1]), "r"(a[2]), "r"(a[3]), "r"(b[0]), "r"(b[1]));
}

// ---------------- kernel 1: convert W -> bf16 (zeroes counts) ----------------
__global__ void __launch_bounds__(256) convert_w_kernel(const float* __restrict__ w) {
    if (blockIdx.x == 0 && threadIdx.x < N_EXPERTS) g_counts[threadIdx.x] = 0;
    const size_t total8 = (size_t)N_EXPERTS * ODIM * KDIM / 8;
    for (size_t i = blockIdx.x * blockDim.x + threadIdx.x; i < total8;
         i += (size_t)gridDim.x * blockDim.x) {
        const float4* src = reinterpret_cast<const float4*>(w) + 2 * i;
        float4 v0 = src[0], v1 = src[1];
        uint4 o;
        o.x = pack_bf16(v0.x, v0.y); o.y = pack_bf16(v0.z, v0.w);
        o.z = pack_bf16(v1.x, v1.y); o.w = pack_bf16(v1.z, v1.w);
        reinterpret_cast<uint4*>(g_ws)[i] = o;
    }
}

// ---------------- kernel 2: bucket tokens (self-probing ids dtype) ----------------
__global__ void bucket_kernel(const void* __restrict__ ids) {
    const uint32_t* idsw = (const uint32_t*)ids;
    const int lane = threadIdx.x & 31;
    uint32_t o = __reduce_or_sync(0xFFFFFFFFu, idsw[2 * lane + 1]);
    const bool is64 = (o == 0);
    int t = blockIdx.x * blockDim.x + threadIdx.x;
    if (t < TOKENS) {
        int e;
        if (is64) e = (int)((const long long*)ids)[t];
        else      e = ((const int*)ids)[t];
        e &= 7;
        int pos = atomicAdd(&g_counts[e], 1);
        g_bucket[e * TOKENS + pos] = t;
    }
}

// ---------------- kernel 3: gather x -> sorted bf16 (full-prefix scan) ----------------
__global__ void __launch_bounds__(256) convert_x_kernel(const float* __restrict__ x) {
    const int r = blockIdx.x;
    int acc = 0, e = 0, off = 0;
    #pragma unroll
    for (int i = 0; i < N_EXPERTS; i++) {
        int nacc = acc + g_counts[i];
        if (r >= acc && r < nacc) { e = i; off = acc; }
        acc = nacc;
    }
    const int token = g_bucket[e * TOKENS + (r - off)];
    const float4* src = reinterpret_cast<const float4*>(x + (size_t)token * KDIM);
    uint4* dst = reinterpret_cast<uint4*>(g_xs + (size_t)r * KDIM);
    const int t = threadIdx.x;
    float4 v0 = src[2 * t], v1 = src[2 * t + 1];
    uint4 o;
    o.x = pack_bf16(v0.x, v0.y); o.y = pack_bf16(v0.z, v0.w);
    o.z = pack_bf16(v1.x, v1.y); o.w = pack_bf16(v1.z, v1.w);
    dst[t] = o;
}

// ---------------- kernel 4: grouped GEMM (1024 thr, warp tile 32x16, 4-stage) ----------------
__global__ void __launch_bounds__(NTHREADS, 1)
moe_gemm_kernel(const float* __restrict__ bias, float* __restrict__ out) {
    extern __shared__ char dynsmem[];

    const int bid = blockIdx.x;
    const int e   = bid / (MT * NT);
    const int rem = bid % (MT * NT);
    const int m0  = (rem / NT) * BM;     // n fastest within expert -> L2 sharing
    const int n0  = (rem % NT) * BN;

    const int cnt = g_counts[e];
    if (m0 >= cnt) return;
    const int rows = min(BM, cnt - m0);
    int off = 0;
    #pragma unroll
    for (int i = 0; i < N_EXPERTS; i++) off += (i < e) ? g_counts[i] : 0;

    const int tid  = threadIdx.x;
    const int wid  = tid >> 5;
    const int lane = tid & 31;
    const int warp_m = wid >> 3;         // 0..3 -> 32-row slice
    const int warp_n = wid & 7;          // 0..7 -> 16-col slice

    const uint32_t sb = (smem_u32(dynsmem) + 127u) & ~127u;

    // ---- cp.async loader: 1024 threads x 16B = 16KB/pass; exactly 1 pass for A and B
    const int lcol = tid & 7;                        // 16B segment within 128B row
    const int lrow = tid >> 3;                       // 0..127
    const uint32_t dof = (uint32_t)lrow * 128u
                       + (((uint32_t)lcol * 16u) ^ ((uint32_t)(lrow & 7) << 4));
    const int ga = min(off + m0 + lrow, TOKENS - 1);
    const char* pA = reinterpret_cast<const char*>(g_xs) + (size_t)ga * (KDIM * 2) + lcol * 16;
    const char* pB = reinterpret_cast<const char*>(g_ws)
                   + ((size_t)e * ODIM + n0 + lrow) * (KDIM * 2) + lcol * 16;

    auto issue = [&](int c, int s) {
        const uint32_t base = sb + (uint32_t)s * STAGE_BYTES;
        const size_t go = (size_t)c * 128;
        CP_ASYNC_CG(base + dof, pA + go);
        CP_ASYNC_CG(base + A_STAGE_BYTES + dof, pB + go);
        CP_COMMIT();
    };

    // ---- compute-side ldmatrix pieces (XOR swizzle, R13-proven)
    const int arow_in = (lane & 15);
    const uint32_t acolu = (uint32_t)((lane >> 4) * 16);
    const int brow = warp_n * 16 + ((lane >> 3) & 1) * 8 + (lane & 7);
    const uint32_t brow_off = (uint32_t)brow * 128u;
    const uint32_t bswz = (uint32_t)(brow & 7) << 4;

    float acc[2][2][4];                  // warp tile 32x16 -> 16 regs
    #pragma unroll
    for (int mi = 0; mi < 2; mi++)
        #pragma unroll
        for (int ni = 0; ni < 2; ni++)
            #pragma unroll
            for (int q = 0; q < 4; q++) acc[mi][ni][q] = 0.f;

    issue(0, 0);
    issue(1, 1);
    issue(2, 2);

    for (int i = 0; i < NCHUNK; i++) {
        CP_WAIT2();                 // uniform depth (3 in flight) -> chunk i landed
        __syncthreads();            // publishes stage i%4; frees stage (i+3)%4
        if (i + 3 < NCHUNK) issue(i + 3, (i + 3) & (STAGES - 1));
        else                CP_COMMIT();   // empty group keeps FIFO depth uniform

        const uint32_t aBase = sb + (uint32_t)(i & (STAGES - 1)) * STAGE_BYTES;
        const uint32_t bBase = aBase + A_STAGE_BYTES;

        #pragma unroll
        for (int ks = 0; ks < 4; ks++) {
            const uint32_t kb = (uint32_t)(ks * 32);
            uint32_t bq[4];              // n16k16 for this warp's 16 cols
            ldsm_x4(bBase + brow_off + ((kb + acolu) ^ bswz),
                    bq[0], bq[1], bq[2], bq[3]);
            uint32_t af[2][4];
            #pragma unroll
            for (int mi = 0; mi < 2; mi++) {
                const int ar = warp_m * 32 + mi * 16 + arow_in;
                const uint32_t col = (kb + acolu) ^ ((uint32_t)(ar & 7) << 4);
                ldsm_x4(aBase + (uint32_t)ar * 128u + col,
                        af[mi][0], af[mi][1], af[mi][2], af[mi][3]);
            }
            #pragma unroll
            for (int mi = 0; mi < 2; mi++)
                #pragma unroll
                for (int ni = 0; ni < 2; ni++) {
                    uint32_t bf[2] = { bq[ni], bq[ni + 2] };
                    mma_16816(acc[mi][ni], af[mi], bf);
                }
        }
    }

    // ---------------- epilogue: bias + bf16-round + fp32 scatter ----------------
    const int group = lane >> 2;
    const int tIn   = lane & 3;
    const float* bp = bias + (size_t)e * ODIM + n0;

    #pragma unroll
    for (int mi = 0; mi < 2; mi++) {
        #pragma unroll
        for (int half = 0; half < 2; half++) {
            const int m = warp_m * 32 + mi * 16 + group + half * 8;
            if (m < rows) {
                const int token = g_bucket[e * TOKENS + m0 + m];
                float* op = out + (size_t)token * ODIM + n0;
                #pragma unroll
                for (int ni = 0; ni < 2; ni++) {
                    const int ncol = warp_n * 16 + ni * 8 + tIn * 2;
                    float2 st;
                    st.x = bf16_round(acc[mi][ni][half * 2 + 0] + bf16_round(bp[ncol]));
                    st.y = bf16_round(acc[mi][ni][half * 2 + 1] + bf16_round(bp[ncol + 1]));
                    *reinterpret_cast<float2*>(op + ncol) = st;
                }
            }
        }
    }
}

// ---------------- launch ----------------
extern "C" void kernel_launch(void* const* d_in, const int* in_sizes, int n_in,
                              void* d_out, int out_size) {
    const float* x    = nullptr;
    const void*  ids  = nullptr;
    const float* w    = nullptr;
    const float* bias = nullptr;
    for (int i = 0; i < n_in; i++) {
        switch (in_sizes[i]) {
            case TOKENS * KDIM:            x    = (const float*)d_in[i]; break;
            case TOKENS:                   ids  = d_in[i];               break;
            case N_EXPERTS * ODIM * KDIM:  w    = (const float*)d_in[i]; break;
            case N_EXPERTS * ODIM:         bias = (const float*)d_in[i]; break;
        }
    }
    (void)out_size;

    cudaFuncSetAttribute(moe_gemm_kernel,
                         cudaFuncAttributeMaxDynamicSharedMemorySize, SMEM_DYN_BYTES);

    convert_w_kernel<<<4096, 256>>>(w);           // also zeroes g_counts
    bucket_kernel<<<TOKENS / 256, 256>>>(ids);    // self-probes ids dtype
    convert_x_kernel<<<TOKENS, 256>>>(x);         // full-prefix scan
    moe_gemm_kernel<<<N_EXPERTS * MT * NT, NTHREADS, SMEM_DYN_BYTES>>>(
        bias, (float*)d_out);
}

// round 16
// speedup vs baseline: 1.2700x; 1.2700x over previous
#include <cuda_runtime.h>
#include <cuda_bf16.h>
#include <cstdint>

// ---------------- problem constants ----------------
#define N_EXPERTS 8
#define TOKENS    8192
#define KDIM      2048
#define ODIM      2048

#define BM 128
#define BN 128
#define BK 64                      // 64 bf16 = 128B per smem row
#define MT (TOKENS / BM)           // 64 worst-case m-tiles per expert
#define NT (ODIM / BN)             // 16
#define NCHUNK (KDIM / BK)         // 32
#define NTHREADS 256
#define STAGES 3
#define A_STAGE_BYTES (BM * 128)   // 16384
#define STAGE_BYTES   (2 * A_STAGE_BYTES)               // 32768
#define SMEM_DYN_BYTES (STAGES * STAGE_BYTES + 128)     // 98432 -> 2 CTAs/SM

// ---------------- device scratch ----------------
__device__ int g_counts[N_EXPERTS];
__device__ int g_bucket[N_EXPERTS * TOKENS];
__device__ __nv_bfloat16 g_xs[TOKENS * KDIM];                 // expert-sorted bf16 x
__device__ __nv_bfloat16 g_ws[N_EXPERTS * ODIM * KDIM];       // bf16 weights

// ---------------- helpers ----------------
__device__ __forceinline__ uint32_t smem_u32(const void* p) {
    uint32_t a;
    asm("{ .reg .u64 t; cvta.to.shared.u64 t, %1; cvt.u32.u64 %0, t; }" : "=r"(a) : "l"(p));
    return a;
}
__device__ __forceinline__ uint32_t pack_bf16(float a, float b) {
    __nv_bfloat162 h = __floats2bfloat162_rn(a, b);
    return *reinterpret_cast<uint32_t*>(&h);
}
__device__ __forceinline__ float bf16_round(float v) {
    return __bfloat162float(__float2bfloat16_rn(v));
}

#define CP_ASYNC_CG(dst, src) \
    asm volatile("cp.async.cg.shared.global [%0], [%1], 16;" :: "r"(dst), "l"(src))
#define CP_COMMIT() asm volatile("cp.async.commit_group;" ::: "memory")
#define CP_WAIT1()  asm volatile("cp.async.wait_group 1;"  ::: "memory")

__device__ __forceinline__ void ldsm_x4(uint32_t addr, uint32_t& r0, uint32_t& r1,
                                        uint32_t& r2, uint32_t& r3) {
    asm volatile("ldmatrix.sync.aligned.m8n8.x4.shared.b16 {%0, %1, %2, %3}, [%4];"
                 : "=r"(r0), "=r"(r1), "=r"(r2), "=r"(r3) : "r"(addr));
}
__device__ __forceinline__ void mma_16816(float* d, const uint32_t* a, const uint32_t* b) {
    asm volatile(
        "mma.sync.aligned.m16n8k16.row.col.f32.bf16.bf16.f32 "
        "{%0, %1, %2, %3}, {%4, %5, %6, %7}, {%8, %9}, {%0, %1, %2, %3};"
        : "+f"(d[0]), "+f"(d[1]), "+f"(d[2]), "+f"(d[3])
        : "r"(a[0]), "r"(a[1]), "r"(a[2]), "r"(a[3]), "r"(b[0]), "r"(b[1]));
}

// ---------------- kernel 1: convert W -> bf16 (zeroes counts) ----------------
__global__ void __launch_bounds__(256) convert_w_kernel(const float* __restrict__ w) {
    if (blockIdx.x == 0 && threadIdx.x < N_EXPERTS) g_counts[threadIdx.x] = 0;
    const size_t total8 = (size_t)N_EXPERTS * ODIM * KDIM / 8;
    for (size_t i = blockIdx.x * blockDim.x + threadIdx.x; i < total8;
         i += (size_t)gridDim.x * blockDim.x) {
        const float4* src = reinterpret_cast<const float4*>(w) + 2 * i;
        float4 v0 = src[0], v1 = src[1];
        uint4 o;
        o.x = pack_bf16(v0.x, v0.y); o.y = pack_bf16(v0.z, v0.w);
        o.z = pack_bf16(v1.x, v1.y); o.w = pack_bf16(v1.z, v1.w);
        reinterpret_cast<uint4*>(g_ws)[i] = o;
    }
}

// ---------------- kernel 2: bucket tokens (self-probing ids dtype) ----------------
__global__ void bucket_kernel(const void* __restrict__ ids) {
    const uint32_t* idsw = (const uint32_t*)ids;
    const int lane = threadIdx.x & 31;
    uint32_t o = __reduce_or_sync(0xFFFFFFFFu, idsw[2 * lane + 1]);
    const bool is64 = (o == 0);
    int t = blockIdx.x * blockDim.x + threadIdx.x;
    if (t < TOKENS) {
        int e;
        if (is64) e = (int)((const long long*)ids)[t];
        else      e = ((const int*)ids)[t];
        e &= 7;
        int pos = atomicAdd(&g_counts[e], 1);
        g_bucket[e * TOKENS + pos] = t;
    }
}

// ---------------- kernel 3: gather x -> sorted bf16 (full-prefix scan) ----------------
__global__ void __launch_bounds__(256) convert_x_kernel(const float* __restrict__ x) {
    const int r = blockIdx.x;
    int acc = 0, e = 0, off = 0;
    #pragma unroll
    for (int i = 0; i < N_EXPERTS; i++) {
        int nacc = acc + g_counts[i];
        if (r >= acc && r < nacc) { e = i; off = acc; }
        acc = nacc;
    }
    const int token = g_bucket[e * TOKENS + (r - off)];
    const float4* src = reinterpret_cast<const float4*>(x + (size_t)token * KDIM);
    uint4* dst = reinterpret_cast<uint4*>(g_xs + (size_t)r * KDIM);
    const int t = threadIdx.x;
    float4 v0 = src[2 * t], v1 = src[2 * t + 1];
    uint4 o;
    o.x = pack_bf16(v0.x, v0.y); o.y = pack_bf16(v0.z, v0.w);
    o.z = pack_bf16(v1.x, v1.y); o.w = pack_bf16(v1.z, v1.w);
    dst[t] = o;
}

// ---------------- kernel 4: grouped GEMM (ks-pipelined fragments) ----------------
__global__ void __launch_bounds__(NTHREADS, 2)
moe_gemm_kernel(const float* __restrict__ bias, float* __restrict__ out) {
    extern __shared__ char dynsmem[];

    const int bid = blockIdx.x;
    const int e   = bid / (MT * NT);
    const int rem = bid % (MT * NT);
    const int m0  = (rem / NT) * BM;     // n fastest within expert -> L2 sharing
    const int n0  = (rem % NT) * BN;

    const int cnt = g_counts[e];
    if (m0 >= cnt) return;
    const int rows = min(BM, cnt - m0);
    int off = 0;
    #pragma unroll
    for (int i = 0; i < N_EXPERTS; i++) off += (i < e) ? g_counts[i] : 0;

    const int tid  = threadIdx.x;
    const int wid  = tid >> 5;
    const int lane = tid & 31;
    const int warp_m = wid >> 2;         // 0..1 -> 64-row slice
    const int warp_n = wid & 3;          // 0..3 -> 32-col slice

    const uint32_t sb = (smem_u32(dynsmem) + 127u) & ~127u;

    // ---- cp.async loader (register-lean): one base per tensor + constant strides
    const int lcol  = tid & 7;                       // 16B segment within 128B row
    const int lrow0 = tid >> 3;                      // 0..31
    const uint32_t dof0 = (uint32_t)lrow0 * 128u
                        + (((uint32_t)lcol * 16u) ^ ((uint32_t)(lrow0 & 7) << 4));
    const int gabase = off + m0 + lrow0;             // A sorted-row base (clamp per j)
    const char* xbase = reinterpret_cast<const char*>(g_xs) + lcol * 16;
    const char* pB0 = reinterpret_cast<const char*>(g_ws)
                    + ((size_t)e * ODIM + n0 + lrow0) * (KDIM * 2) + lcol * 16;

    auto issue = [&](int c, int s) {
        const uint32_t base = sb + (uint32_t)s * STAGE_BYTES;
        const size_t go = (size_t)c * 128;
        #pragma unroll
        for (int j = 0; j < 4; j++) {
            const int ga = min(gabase + 32 * j, TOKENS - 1);   // per-j clamp (correct at tail)
            CP_ASYNC_CG(base + dof0 + (uint32_t)j * 4096u,
                        xbase + (size_t)ga * (KDIM * 2) + go);
        }
        #pragma unroll
        for (int j = 0; j < 4; j++)
            CP_ASYNC_CG(base + A_STAGE_BYTES + dof0 + (uint32_t)j * 4096u,
                        pB0 + (size_t)j * (32 * KDIM * 2) + go);
        CP_COMMIT();
    };

    // ---- compute-side ldmatrix pieces (XOR swizzle)
    const int arow_in = (lane & 15);
    const uint32_t acolu = (uint32_t)((lane >> 4) * 16);
    const int brow_in = ((lane >> 3) & 1) * 8 + (lane & 7);

    float acc[4][4][4];
    #pragma unroll
    for (int mi = 0; mi < 4; mi++)
        #pragma unroll
        for (int ni = 0; ni < 4; ni++)
            #pragma unroll
            for (int q = 0; q < 4; q++) acc[mi][ni][q] = 0.f;

    issue(0, 0);
    issue(1, 1);

    // double-buffered fragments: load ks+1 before issuing ks's MMAs
    uint32_t afb[2][4][4], bqb[2][2][4];

    for (int i = 0; i < NCHUNK; i++) {
        CP_WAIT1();
        __syncthreads();            // publishes stage i%3; frees stage (i+2)%3
        if (i + 2 < NCHUNK) issue(i + 2, (i + 2) % STAGES);
        else                CP_COMMIT();   // uniform FIFO depth

        const uint32_t aBase = sb + (uint32_t)(i % STAGES) * STAGE_BYTES;
        const uint32_t bBase = aBase + A_STAGE_BYTES;

        auto load_frags = [&](int ks, uint32_t af[4][4], uint32_t bq[2][4]) {
            const uint32_t kb = (uint32_t)(ks * 32);
            #pragma unroll
            for (int h = 0; h < 2; h++) {
                const int br = warp_n * 32 + h * 16 + brow_in;
                const uint32_t col = (kb + acolu) ^ ((uint32_t)(br & 7) << 4);
                ldsm_x4(bBase + (uint32_t)br * 128u + col,
                        bq[h][0], bq[h][1], bq[h][2], bq[h][3]);
            }
            #pragma unroll
            for (int mi = 0; mi < 4; mi++) {
                const int ar = warp_m * 64 + mi * 16 + arow_in;
                const uint32_t col = (kb + acolu) ^ ((uint32_t)(ar & 7) << 4);
                ldsm_x4(aBase + (uint32_t)ar * 128u + col,
                        af[mi][0], af[mi][1], af[mi][2], af[mi][3]);
            }
        };

        load_frags(0, afb[0], bqb[0]);
        #pragma unroll
        for (int ks = 0; ks < 4; ks++) {
            const int cur = ks & 1;
            if (ks < 3) load_frags(ks + 1, afb[cur ^ 1], bqb[cur ^ 1]);
            #pragma unroll
            for (int mi = 0; mi < 4; mi++)
                #pragma unroll
                for (int ni = 0; ni < 4; ni++) {
                    uint32_t bf[2] = { bqb[cur][ni >> 1][ni & 1],
                                       bqb[cur][ni >> 1][(ni & 1) + 2] };
                    mma_16816(acc[mi][ni], afb[cur][mi], bf);
                }
        }
    }

    // ---------------- epilogue: bias + bf16-round + fp32 scatter ----------------
    const int group = lane >> 2;
    const int tIn   = lane & 3;
    const float* bp = bias + (size_t)e * ODIM + n0;

    #pragma unroll
    for (int mi = 0; mi < 4; mi++) {
        #pragma unroll
        for (int half = 0; half < 2; half++) {
            const int m = warp_m * 64 + mi * 16 + group + half * 8;
            if (m < rows) {
                const int token = g_bucket[e * TOKENS + m0 + m];
                float* op = out + (size_t)token * ODIM + n0;
                #pragma unroll
                for (int ni = 0; ni < 4; ni++) {
                    const int ncol = warp_n * 32 + ni * 8 + tIn * 2;
                    float2 st;
                    st.x = bf16_round(acc[mi][ni][half * 2 + 0] + bf16_round(bp[ncol]));
                    st.y = bf16_round(acc[mi][ni][half * 2 + 1] + bf16_round(bp[ncol + 1]));
                    *reinterpret_cast<float2*>(op + ncol) = st;
                }
            }
        }
    }
}

// ---------------- launch ----------------
extern "C" void kernel_launch(void* const* d_in, const int* in_sizes, int n_in,
                              void* d_out, int out_size) {
    const float* x    = nullptr;
    const void*  ids  = nullptr;
    const float* w    = nullptr;
    const float* bias = nullptr;
    for (int i = 0; i < n_in; i++) {
        switch (in_sizes[i]) {
            case TOKENS * KDIM:            x    = (const float*)d_in[i]; break;
            case TOKENS:                   ids  = d_in[i];               break;
            case N_EXPERTS * ODIM * KDIM:  w    = (const float*)d_in[i]; break;
            case N_EXPERTS * ODIM:         bias = (const float*)d_in[i]; break;
        }
    }
    (void)out_size;

    cudaFuncSetAttribute(moe_gemm_kernel,
                         cudaFuncAttributeMaxDynamicSharedMemorySize, SMEM_DYN_BYTES);

    convert_w_kernel<<<4096, 256>>>(w);           // also zeroes g_counts
    bucket_kernel<<<TOKENS / 256, 256>>>(ids);    // self-probes ids dtype
    convert_x_kernel<<<TOKENS, 256>>>(x);         // full-prefix scan
    moe_gemm_kernel<<<N_EXPERTS * MT * NT, NTHREADS, SMEM_DYN_BYTES>>>(
        bias, (float*)d_out);
}